// round 5
// baseline (speedup 1.0000x reference)
#include <cuda_runtime.h>
#include <stdint.h>
#include <math.h>

#define BB 4
#define SS 2048
#define DD 512
#define HH 8

// ---------------- scratch (allocation-free: __device__ globals) ----------------
__device__ float g_q[BB * HH * SS * 64];    // (B,H,S,64)  tf32-rounded, pre-scaled by 0.125
__device__ float g_k[BB * HH * SS * 64];    // (B,H,S,64)  tf32-rounded
__device__ float g_v[BB * HH * 64 * SS];    // (B,H,64,S)  d-major, tf32-rounded
__device__ float g_ctx[BB * SS * DD];       // (B,S,512)

// ---------------- helpers ----------------
__device__ __forceinline__ uint32_t f2tf(float x) {
    uint32_t r;
    asm("cvt.rna.tf32.f32 %0, %1;" : "=r"(r) : "f"(x));
    return r;
}

__device__ __forceinline__ void mma_tf32(float* c, const uint32_t* a, const uint32_t* b) {
    asm volatile(
        "mma.sync.aligned.m16n8k8.row.col.f32.tf32.tf32.f32 "
        "{%0,%1,%2,%3}, {%4,%5,%6,%7}, {%8,%9}, {%0,%1,%2,%3};\n"
        : "+f"(c[0]), "+f"(c[1]), "+f"(c[2]), "+f"(c[3])
        : "r"(a[0]), "r"(a[1]), "r"(a[2]), "r"(a[3]), "r"(b[0]), "r"(b[1]));
}

// ---------------- tensor-core SGEMM (HMMA tf32), proven in R2 ----------------
// MODE 0: plain C[m][n] float. MODE 1: split-head (B,H,S,64), tf32-rounded, *scale.
// MODE 2: split-head d-major (B,H,64,S), tf32-rounded.
template <int MODE>
__global__ __launch_bounds__(256) void gemm_tc(
    const float* __restrict__ A, const float* __restrict__ W,
    const float* __restrict__ bias, float* __restrict__ C,
    int M, int K, int N, float scale)
{
    __shared__ uint32_t As[16][132];
    __shared__ uint32_t Ws[16][68];

    const int tid = threadIdx.x;
    const int lane = tid & 31, warp = tid >> 5;
    const int gid = lane >> 2, t4 = lane & 3;
    const int wm = warp & 3, wn = warp >> 2;
    const int m0 = blockIdx.y * 128, n0 = blockIdx.x * 64;

    const int ar = tid >> 1, ac = (tid & 1) * 8;
    const int br = tid >> 4, bc = (tid & 15) * 4;

    const float* Aptr = A + (size_t)(m0 + ar) * K + ac;
    const float* Wptr = W + (size_t)br * N + n0 + bc;

    float acc[2][4][4];
#pragma unroll
    for (int i = 0; i < 2; i++)
#pragma unroll
        for (int j = 0; j < 4; j++)
#pragma unroll
            for (int k = 0; k < 4; k++) acc[i][j][k] = 0.0f;

    float4 apre0 = *reinterpret_cast<const float4*>(Aptr);
    float4 apre1 = *reinterpret_cast<const float4*>(Aptr + 4);
    float4 wpre  = *reinterpret_cast<const float4*>(Wptr);

    for (int k0 = 0; k0 < K; k0 += 16) {
        As[ac + 0][ar] = f2tf(apre0.x);
        As[ac + 1][ar] = f2tf(apre0.y);
        As[ac + 2][ar] = f2tf(apre0.z);
        As[ac + 3][ar] = f2tf(apre0.w);
        As[ac + 4][ar] = f2tf(apre1.x);
        As[ac + 5][ar] = f2tf(apre1.y);
        As[ac + 6][ar] = f2tf(apre1.z);
        As[ac + 7][ar] = f2tf(apre1.w);
        Ws[br][bc + 0] = f2tf(wpre.x);
        Ws[br][bc + 1] = f2tf(wpre.y);
        Ws[br][bc + 2] = f2tf(wpre.z);
        Ws[br][bc + 3] = f2tf(wpre.w);
        __syncthreads();

        if (k0 + 16 < K) {
            apre0 = *reinterpret_cast<const float4*>(Aptr + k0 + 16);
            apre1 = *reinterpret_cast<const float4*>(Aptr + k0 + 20);
            wpre  = *reinterpret_cast<const float4*>(Wptr + (size_t)(k0 + 16) * N);
        }

#pragma unroll
        for (int ks = 0; ks < 2; ks++) {
            const int kk = ks * 8;
            uint32_t af[2][4], bf[4][2];
#pragma unroll
            for (int mf = 0; mf < 2; mf++) {
                const int mr = wm * 32 + mf * 16 + gid;
                af[mf][0] = As[kk + t4][mr];
                af[mf][1] = As[kk + t4][mr + 8];
                af[mf][2] = As[kk + t4 + 4][mr];
                af[mf][3] = As[kk + t4 + 4][mr + 8];
            }
#pragma unroll
            for (int nf = 0; nf < 4; nf++) {
                const int nc = wn * 32 + nf * 8 + gid;
                bf[nf][0] = Ws[kk + t4][nc];
                bf[nf][1] = Ws[kk + t4 + 4][nc];
            }
#pragma unroll
            for (int mf = 0; mf < 2; mf++)
#pragma unroll
                for (int nf = 0; nf < 4; nf++)
                    mma_tf32(acc[mf][nf], af[mf], bf[nf]);
        }
        __syncthreads();
    }

#pragma unroll
    for (int mf = 0; mf < 2; mf++) {
#pragma unroll
        for (int half = 0; half < 2; half++) {
            const int m = m0 + wm * 32 + mf * 16 + gid + half * 8;
#pragma unroll
            for (int nf = 0; nf < 4; nf++) {
                const int n = n0 + wn * 32 + nf * 8 + t4 * 2;
                float vx = acc[mf][nf][half * 2 + 0] + bias[n];
                float vy = acc[mf][nf][half * 2 + 1] + bias[n + 1];
                if (MODE == 0) {
                    *reinterpret_cast<float2*>(&C[(size_t)m * N + n]) =
                        make_float2(vx, vy);
                } else if (MODE == 1) {
                    const int b = m >> 11, s = m & 2047;
                    const int h = n >> 6, d = n & 63;
                    float2 v = make_float2(__uint_as_float(f2tf(vx * scale)),
                                           __uint_as_float(f2tf(vy * scale)));
                    *reinterpret_cast<float2*>(
                        &C[(((size_t)(b * HH + h)) * SS + s) * 64 + d]) = v;
                } else {
                    const int b = m >> 11, s = m & 2047;
                    const int h = n >> 6, d = n & 63;
                    float* base = &C[(((size_t)(b * HH + h)) * 64 + d) * SS + s];
                    base[0]  = __uint_as_float(f2tf(vx));
                    base[SS] = __uint_as_float(f2tf(vy));
                }
            }
        }
    }
}

// ---------------- HMMA flash attention, M-blocked, fixed-shift softmax ----------------
// CTA: 128 threads (4 warps), 128 queries; warp w owns rows w*32..w*32+31.
// 32 key tiles of 64. Q lives in registers for the whole kernel. No online max,
// no accumulator rescale (fixed per-row shift mq preserves ref fp32 absorption).
__global__ __launch_bounds__(128) void attn_hmma(
    const float* __restrict__ Q, const float* __restrict__ K,
    const float* __restrict__ V, const int* __restrict__ mask,
    float* __restrict__ ctx)
{
    __shared__ float Ks[64][68];   // [key][d]   tf32 bits
    __shared__ float Vt[64][68];   // [d][key]   tf32 bits (V is d-major in gmem)
    __shared__ float Mk[64];

    const int tid = threadIdx.x;
    const int lane = tid & 31, warp = tid >> 5;
    const int gid = lane >> 2, t4 = lane & 3;
    const int bh = blockIdx.y, b = bh >> 3, h = bh & 7;
    const int q0 = blockIdx.x * 128;
    const int rowbase = q0 + warp * 32;

    const float* Qb = Q + (size_t)bh * SS * 64;
    const float* Kb = K + (size_t)bh * SS * 64;
    const float* Vb = V + (size_t)bh * 64 * SS;
    const int* mrow = mask + b * SS;

    // Q a-fragments in registers (already tf32 bits, pre-scaled by 0.125)
    uint32_t qa[2][8][4];
#pragma unroll
    for (int mf = 0; mf < 2; mf++) {
        const float* qr1 = Qb + (size_t)(rowbase + mf * 16 + gid) * 64;
        const float* qr2 = qr1 + 8 * 64;
#pragma unroll
        for (int kf = 0; kf < 8; kf++) {
            qa[mf][kf][0] = __float_as_uint(qr1[kf * 8 + t4]);
            qa[mf][kf][1] = __float_as_uint(qr2[kf * 8 + t4]);
            qa[mf][kf][2] = __float_as_uint(qr1[kf * 8 + t4 + 4]);
            qa[mf][kf][3] = __float_as_uint(qr2[kf * 8 + t4 + 4]);
        }
    }

    float mqv[4];   // per-row query mask (rows: mf*16 + half*8 + gid)
#pragma unroll
    for (int r = 0; r < 4; r++)
        mqv[r] = mrow[rowbase + (r >> 1) * 16 + (r & 1) * 8 + gid] ? 0.0f : -1e9f;

    float acc[2][8][4];
#pragma unroll
    for (int mf = 0; mf < 2; mf++)
#pragma unroll
        for (int nf = 0; nf < 8; nf++)
#pragma unroll
            for (int e = 0; e < 4; e++) acc[mf][nf][e] = 0.0f;
    float l[4] = {0.0f, 0.0f, 0.0f, 0.0f};

    const int fr = tid >> 1, fc = (tid & 1) * 32;
    const int quad = lane & 28;   // gid*4

    for (int k0 = 0; k0 < SS; k0 += 64) {
        __syncthreads();   // previous tile's smem reads complete
        {
            const float4* kp = reinterpret_cast<const float4*>(Kb + (size_t)(k0 + fr) * 64 + fc);
            const float4* vp = reinterpret_cast<const float4*>(Vb + (size_t)fr * SS + k0 + fc);
#pragma unroll
            for (int i = 0; i < 8; i++) {
                *reinterpret_cast<float4*>(&Ks[fr][fc + i * 4]) = kp[i];
                *reinterpret_cast<float4*>(&Vt[fr][fc + i * 4]) = vp[i];
            }
            if (tid < 64) Mk[tid] = mrow[k0 + tid] ? 0.0f : -1e9f;
        }
        __syncthreads();

        // ---- S = Q @ K^T : 32x64 per warp ----
        float sf[2][8][4];
#pragma unroll
        for (int mf = 0; mf < 2; mf++)
#pragma unroll
            for (int nf = 0; nf < 8; nf++)
#pragma unroll
                for (int e = 0; e < 4; e++) sf[mf][nf][e] = 0.0f;
#pragma unroll
        for (int kf = 0; kf < 8; kf++) {
#pragma unroll
            for (int nf = 0; nf < 8; nf++) {
                uint32_t bf[2];
                bf[0] = __float_as_uint(Ks[nf * 8 + gid][kf * 8 + t4]);
                bf[1] = __float_as_uint(Ks[nf * 8 + gid][kf * 8 + t4 + 4]);
                mma_tf32(sf[0][nf], qa[0][kf], bf);
                mma_tf32(sf[1][nf], qa[1][kf], bf);
            }
        }

        // ---- masked softmax, fixed shift (ref fp32 absorption preserved) ----
#pragma unroll
        for (int nf = 0; nf < 8; nf++) {
            const float2 mk2 = *reinterpret_cast<const float2*>(&Mk[nf * 8 + t4 * 2]);
#pragma unroll
            for (int mf = 0; mf < 2; mf++) {
                const float mqa = mqv[mf * 2], mqb = mqv[mf * 2 + 1];
                float t0 = (sf[mf][nf][0] + mk2.x) + mqa;
                float t1 = (sf[mf][nf][1] + mk2.y) + mqa;
                float t2 = (sf[mf][nf][2] + mk2.x) + mqb;
                float t3 = (sf[mf][nf][3] + mk2.y) + mqb;
                float p0 = __expf(t0 - mqa);
                float p1 = __expf(t1 - mqa);
                float p2 = __expf(t2 - mqb);
                float p3 = __expf(t3 - mqb);
                l[mf * 2]     += p0 + p1;
                l[mf * 2 + 1] += p2 + p3;
                sf[mf][nf][0] = __uint_as_float(f2tf(p0));
                sf[mf][nf][1] = __uint_as_float(f2tf(p1));
                sf[mf][nf][2] = __uint_as_float(f2tf(p2));
                sf[mf][nf][3] = __uint_as_float(f2tf(p3));
            }
        }

        // ---- O += P @ V : shfl-transpose P C-frags into A-frags ----
        const int s1 = quad + (t4 >> 1);        // owner of col t4 (and row pair)
        const int s2 = s1 + 2;                  // owner of col t4+4
        const bool odd = (t4 & 1);
#pragma unroll
        for (int kf = 0; kf < 8; kf++) {
            uint32_t vb[8][2];
#pragma unroll
            for (int nf = 0; nf < 8; nf++) {
                vb[nf][0] = __float_as_uint(Vt[nf * 8 + gid][kf * 8 + t4]);
                vb[nf][1] = __float_as_uint(Vt[nf * 8 + gid][kf * 8 + t4 + 4]);
            }
#pragma unroll
            for (int mf = 0; mf < 2; mf++) {
                // transpose 16x8 tile sf[mf][kf] (C-frag) -> A-frag
                uint32_t c0 = __float_as_uint(sf[mf][kf][0]);
                uint32_t c1 = __float_as_uint(sf[mf][kf][1]);
                uint32_t c2 = __float_as_uint(sf[mf][kf][2]);
                uint32_t c3 = __float_as_uint(sf[mf][kf][3]);
                uint32_t a[4];
                uint32_t x0 = __shfl_sync(0xffffffffu, c0, s1);
                uint32_t x1 = __shfl_sync(0xffffffffu, c1, s1);
                uint32_t y0 = __shfl_sync(0xffffffffu, c2, s1);
                uint32_t y1 = __shfl_sync(0xffffffffu, c3, s1);
                a[0] = odd ? x1 : x0;
                a[1] = odd ? y1 : y0;
                x0 = __shfl_sync(0xffffffffu, c0, s2);
                x1 = __shfl_sync(0xffffffffu, c1, s2);
                y0 = __shfl_sync(0xffffffffu, c2, s2);
                y1 = __shfl_sync(0xffffffffu, c3, s2);
                a[2] = odd ? x1 : x0;
                a[3] = odd ? y1 : y0;
#pragma unroll
                for (int nf = 0; nf < 8; nf++)
                    mma_tf32(acc[mf][nf], a, vb[nf]);
            }
        }
    }

    // final: reduce l across the quad (4 lanes cover a full row)
#pragma unroll
    for (int r = 0; r < 4; r++) {
        l[r] += __shfl_xor_sync(0xffffffffu, l[r], 1);
        l[r] += __shfl_xor_sync(0xffffffffu, l[r], 2);
    }

    // epilogue: normalize + write ctx (B,S,H*64)
#pragma unroll
    for (int mf = 0; mf < 2; mf++) {
#pragma unroll
        for (int half = 0; half < 2; half++) {
            const int row = rowbase + mf * 16 + half * 8 + gid;
            const float inv = 1.0f / l[mf * 2 + half];
            float* out = ctx + ((size_t)(b * SS + row)) * DD + h * 64;
#pragma unroll
            for (int nf = 0; nf < 8; nf++) {
                *reinterpret_cast<float2*>(&out[nf * 8 + t4 * 2]) =
                    make_float2(acc[mf][nf][half * 2] * inv,
                                acc[mf][nf][half * 2 + 1] * inv);
            }
        }
    }
}

// ---------------- launch ----------------
extern "C" void kernel_launch(void* const* d_in, const int* in_sizes, int n_in,
                              void* d_out, int out_size)
{
    (void)in_sizes; (void)n_in; (void)out_size;
    const float* query = (const float*)d_in[0];
    const float* value = (const float*)d_in[1];
    const int*   amask = (const int*)d_in[2];
    const float* Wq = (const float*)d_in[3];
    const float* bq = (const float*)d_in[4];
    const float* Wk = (const float*)d_in[5];
    const float* bk = (const float*)d_in[6];
    const float* Wv = (const float*)d_in[7];
    const float* bv = (const float*)d_in[8];
    const float* Wo = (const float*)d_in[9];
    const float* bo = (const float*)d_in[10];
    float* out = (float*)d_out;

    float *pq, *pk, *pv, *pctx;
    cudaGetSymbolAddress((void**)&pq, g_q);
    cudaGetSymbolAddress((void**)&pk, g_k);
    cudaGetSymbolAddress((void**)&pv, g_v);
    cudaGetSymbolAddress((void**)&pctx, g_ctx);

    const int M = BB * SS;              // 8192
    const dim3 ggrid(DD / 64, M / 128); // (8, 64)

    gemm_tc<1><<<ggrid, 256>>>(query, Wq, bq, pq, M, DD, DD, 0.125f);  // Q (pre-scaled)
    gemm_tc<1><<<ggrid, 256>>>(value, Wk, bk, pk, M, DD, DD, 1.0f);    // K
    gemm_tc<2><<<ggrid, 256>>>(value, Wv, bv, pv, M, DD, DD, 1.0f);    // V (d-major)

    attn_hmma<<<dim3(SS / 128, BB * HH), 128>>>(pq, pk, pv, amask, pctx);

    gemm_tc<0><<<ggrid, 256>>>(pctx, Wo, bo, out, M, DD, DD, 1.0f);    // out proj
}

// round 6
// speedup vs baseline: 1.4678x; 1.4678x over previous
#include <cuda_runtime.h>
#include <stdint.h>
#include <math.h>

#define BB 4
#define SS 2048
#define DD 512
#define HH 8

// ---------------- scratch (allocation-free: __device__ globals) ----------------
__device__ float g_q[BB * HH * SS * 64];    // (B,H,S,64)  tf32-rounded, pre-scaled by 0.125
__device__ float g_k[BB * HH * SS * 64];    // (B,H,S,64)  tf32-rounded
__device__ float g_v[BB * HH * SS * 64];    // (B,H,S,64)  tf32-rounded
__device__ float g_ctx[BB * SS * DD];       // (B,S,512)

// ---------------- helpers ----------------
__device__ __forceinline__ uint32_t f2tf(float x) {
    uint32_t r;
    asm("cvt.rna.tf32.f32 %0, %1;" : "=r"(r) : "f"(x));
    return r;
}

__device__ __forceinline__ void mma_tf32(float* c, const uint32_t* a, const uint32_t* b) {
    asm volatile(
        "mma.sync.aligned.m16n8k8.row.col.f32.tf32.tf32.f32 "
        "{%0,%1,%2,%3}, {%4,%5,%6,%7}, {%8,%9}, {%0,%1,%2,%3};\n"
        : "+f"(c[0]), "+f"(c[1]), "+f"(c[2]), "+f"(c[3])
        : "r"(a[0]), "r"(a[1]), "r"(a[2]), "r"(a[3]), "r"(b[0]), "r"(b[1]));
}

__device__ __forceinline__ uint32_t smem_u32(const void* p) {
    uint32_t a;
    asm("{ .reg .u64 t; cvta.to.shared.u64 t, %1; cvt.u32.u64 %0, t; }" : "=r"(a) : "l"(p));
    return a;
}
__device__ __forceinline__ void cpa16(uint32_t dst, const void* src) {
    asm volatile("cp.async.cg.shared.global [%0], [%1], 16;" :: "r"(dst), "l"(src));
}

// ---------------- tensor-core SGEMM (HMMA tf32), proven in R2 ----------------
// MODE 0: plain C[m][n] float. MODE 1: split-head (B,H,S,64), tf32-rounded, *scale.
template <int MODE>
__global__ __launch_bounds__(256) void gemm_tc(
    const float* __restrict__ A, const float* __restrict__ W,
    const float* __restrict__ bias, float* __restrict__ C,
    int M, int K, int N, float scale)
{
    __shared__ uint32_t As[16][132];
    __shared__ uint32_t Ws[16][68];

    const int tid = threadIdx.x;
    const int lane = tid & 31, warp = tid >> 5;
    const int gid = lane >> 2, t4 = lane & 3;
    const int wm = warp & 3, wn = warp >> 2;
    const int m0 = blockIdx.y * 128, n0 = blockIdx.x * 64;

    const int ar = tid >> 1, ac = (tid & 1) * 8;
    const int br = tid >> 4, bc = (tid & 15) * 4;

    const float* Aptr = A + (size_t)(m0 + ar) * K + ac;
    const float* Wptr = W + (size_t)br * N + n0 + bc;

    float acc[2][4][4];
#pragma unroll
    for (int i = 0; i < 2; i++)
#pragma unroll
        for (int j = 0; j < 4; j++)
#pragma unroll
            for (int k = 0; k < 4; k++) acc[i][j][k] = 0.0f;

    float4 apre0 = *reinterpret_cast<const float4*>(Aptr);
    float4 apre1 = *reinterpret_cast<const float4*>(Aptr + 4);
    float4 wpre  = *reinterpret_cast<const float4*>(Wptr);

    for (int k0 = 0; k0 < K; k0 += 16) {
        As[ac + 0][ar] = f2tf(apre0.x);
        As[ac + 1][ar] = f2tf(apre0.y);
        As[ac + 2][ar] = f2tf(apre0.z);
        As[ac + 3][ar] = f2tf(apre0.w);
        As[ac + 4][ar] = f2tf(apre1.x);
        As[ac + 5][ar] = f2tf(apre1.y);
        As[ac + 6][ar] = f2tf(apre1.z);
        As[ac + 7][ar] = f2tf(apre1.w);
        Ws[br][bc + 0] = f2tf(wpre.x);
        Ws[br][bc + 1] = f2tf(wpre.y);
        Ws[br][bc + 2] = f2tf(wpre.z);
        Ws[br][bc + 3] = f2tf(wpre.w);
        __syncthreads();

        if (k0 + 16 < K) {
            apre0 = *reinterpret_cast<const float4*>(Aptr + k0 + 16);
            apre1 = *reinterpret_cast<const float4*>(Aptr + k0 + 20);
            wpre  = *reinterpret_cast<const float4*>(Wptr + (size_t)(k0 + 16) * N);
        }

#pragma unroll
        for (int ks = 0; ks < 2; ks++) {
            const int kk = ks * 8;
            uint32_t af[2][4], bf[4][2];
#pragma unroll
            for (int mf = 0; mf < 2; mf++) {
                const int mr = wm * 32 + mf * 16 + gid;
                af[mf][0] = As[kk + t4][mr];
                af[mf][1] = As[kk + t4][mr + 8];
                af[mf][2] = As[kk + t4 + 4][mr];
                af[mf][3] = As[kk + t4 + 4][mr + 8];
            }
#pragma unroll
            for (int nf = 0; nf < 4; nf++) {
                const int nc = wn * 32 + nf * 8 + gid;
                bf[nf][0] = Ws[kk + t4][nc];
                bf[nf][1] = Ws[kk + t4 + 4][nc];
            }
#pragma unroll
            for (int mf = 0; mf < 2; mf++)
#pragma unroll
                for (int nf = 0; nf < 4; nf++)
                    mma_tf32(acc[mf][nf], af[mf], bf[nf]);
        }
        __syncthreads();
    }

#pragma unroll
    for (int mf = 0; mf < 2; mf++) {
#pragma unroll
        for (int half = 0; half < 2; half++) {
            const int m = m0 + wm * 32 + mf * 16 + gid + half * 8;
#pragma unroll
            for (int nf = 0; nf < 4; nf++) {
                const int n = n0 + wn * 32 + nf * 8 + t4 * 2;
                float vx = acc[mf][nf][half * 2 + 0] + bias[n];
                float vy = acc[mf][nf][half * 2 + 1] + bias[n + 1];
                if (MODE == 0) {
                    *reinterpret_cast<float2*>(&C[(size_t)m * N + n]) =
                        make_float2(vx, vy);
                } else {
                    const int b = m >> 11, s = m & 2047;
                    const int h = n >> 6, d = n & 63;
                    float2 v = make_float2(__uint_as_float(f2tf(vx * scale)),
                                           __uint_as_float(f2tf(vy * scale)));
                    *reinterpret_cast<float2*>(
                        &C[(((size_t)(b * HH + h)) * SS + s) * 64 + d]) = v;
                }
            }
        }
    }
}

// ---------------- HMMA flash attention: cp.async double-buffered, fixed-shift ----------------
// CTA: 128 threads (4 warps), 64 queries, 16 rows/warp. 32 key tiles of 64.
// Pads: K rows 68 words (QK B-frag banks 4*gid+t4, CF), V rows 72 ([key][d] s-major,
// PV B-frag banks 8*t4+gid, CF). No online max / rescale (fixed shift mq).
#define KPAD 68
#define VPAD 72
#define AKS(buf, r, c) (sm_f + (buf) * (64 * KPAD) + (r) * KPAD + (c))
#define AVS(buf, r, c) (sm_f + 2 * 64 * KPAD + (buf) * (64 * VPAD) + (r) * VPAD + (c))
#define AMK(buf, i)    (sm_f + 2 * 64 * KPAD + 2 * 64 * VPAD + (buf) * 64 + (i))
#define SMEM_FLOATS    (2 * 64 * KPAD + 2 * 64 * VPAD + 128)
#define NT (SS / 64)

__global__ __launch_bounds__(128, 3) void attn_hmma(
    const float* __restrict__ Q, const float* __restrict__ K,
    const float* __restrict__ V, const int* __restrict__ mask,
    float* __restrict__ ctx)
{
    extern __shared__ float sm_f[];
    const uint32_t smb = smem_u32(sm_f);

    const int tid = threadIdx.x;
    const int lane = tid & 31, warp = tid >> 5;
    const int gid = lane >> 2, t4 = lane & 3;
    const int bh = blockIdx.y, b = bh >> 3, h = bh & 7;
    const int q0 = blockIdx.x * 64;

    const float* Qb = Q + (size_t)bh * SS * 64;
    const float* Kb = K + (size_t)bh * SS * 64;
    const float* Vb = V + (size_t)bh * SS * 64;
    const int* mrow = mask + b * SS;

    // Q a-fragments in registers (tf32 bits, pre-scaled by 0.125)
    uint32_t qa[8][4];
    {
        const float* qr1 = Qb + (size_t)(q0 + warp * 16 + gid) * 64;
        const float* qr2 = qr1 + 8 * 64;
#pragma unroll
        for (int kf = 0; kf < 8; kf++) {
            qa[kf][0] = __float_as_uint(qr1[kf * 8 + t4]);
            qa[kf][1] = __float_as_uint(qr2[kf * 8 + t4]);
            qa[kf][2] = __float_as_uint(qr1[kf * 8 + t4 + 4]);
            qa[kf][3] = __float_as_uint(qr2[kf * 8 + t4 + 4]);
        }
    }
    const float mq1 = mrow[q0 + warp * 16 + gid] ? 0.0f : -1e9f;
    const float mq2 = mrow[q0 + warp * 16 + gid + 8] ? 0.0f : -1e9f;

    float acc[8][4];
#pragma unroll
    for (int nf = 0; nf < 8; nf++)
#pragma unroll
        for (int e = 0; e < 4; e++) acc[nf][e] = 0.0f;
    float l1 = 0.0f, l2 = 0.0f;

    // async fill assignment: thread copies 8x16B of K and 8x16B of V
    const int fr = tid >> 1, fcw = (tid & 1) * 32;  // row, word col base

    // prologue: tile 0 -> buf 0
    {
        const float* kp = Kb + (size_t)fr * 64 + fcw;
        const float* vp = Vb + (size_t)fr * 64 + fcw;
#pragma unroll
        for (int i = 0; i < 8; i++) {
            cpa16(smb + 4 * (uint32_t)(0 * (64 * KPAD) + fr * KPAD + fcw + i * 4), kp + i * 4);
            cpa16(smb + 4 * (uint32_t)(2 * 64 * KPAD + 0 * (64 * VPAD) + fr * VPAD + fcw + i * 4), vp + i * 4);
        }
        asm volatile("cp.async.commit_group;");
        if (tid < 64) *AMK(0, tid) = mrow[tid] ? 0.0f : -1e9f;
    }

    const int s1 = (lane & 28) + (t4 >> 1);  // shfl-transpose sources
    const int s2 = s1 + 2;
    const bool odd = (t4 & 1);

    for (int t = 0; t < NT; t++) {
        const int cur = t & 1;
        if (t + 1 < NT) {
            const int nxt = cur ^ 1, k1 = (t + 1) * 64;
            const float* kp = Kb + (size_t)(k1 + fr) * 64 + fcw;
            const float* vp = Vb + (size_t)(k1 + fr) * 64 + fcw;
#pragma unroll
            for (int i = 0; i < 8; i++) {
                cpa16(smb + 4 * (uint32_t)(nxt * (64 * KPAD) + fr * KPAD + fcw + i * 4), kp + i * 4);
                cpa16(smb + 4 * (uint32_t)(2 * 64 * KPAD + nxt * (64 * VPAD) + fr * VPAD + fcw + i * 4), vp + i * 4);
            }
            asm volatile("cp.async.commit_group;");
            if (tid < 64) *AMK(nxt, tid) = mrow[k1 + tid] ? 0.0f : -1e9f;
            asm volatile("cp.async.wait_group 1;");
        } else {
            asm volatile("cp.async.wait_group 0;");
        }
        __syncthreads();

        // ---- S = Q @ K^T : 16x64 per warp ----
        float sf[8][4];
#pragma unroll
        for (int nf = 0; nf < 8; nf++)
#pragma unroll
            for (int e = 0; e < 4; e++) sf[nf][e] = 0.0f;
#pragma unroll
        for (int kf = 0; kf < 8; kf++) {
#pragma unroll
            for (int nf = 0; nf < 8; nf++) {
                uint32_t bf[2];
                bf[0] = __float_as_uint(*AKS(cur, nf * 8 + gid, kf * 8 + t4));
                bf[1] = __float_as_uint(*AKS(cur, nf * 8 + gid, kf * 8 + t4 + 4));
                mma_tf32(sf[nf], qa[kf], bf);
            }
        }

        // ---- masked softmax, fixed shift (ref fp32 absorption preserved) ----
#pragma unroll
        for (int nf = 0; nf < 8; nf++) {
            const float mk0 = *AMK(cur, nf * 8 + t4 * 2);
            const float mk1 = *AMK(cur, nf * 8 + t4 * 2 + 1);
            float p0 = __expf(((sf[nf][0] + mk0) + mq1) - mq1);
            float p1 = __expf(((sf[nf][1] + mk1) + mq1) - mq1);
            float p2 = __expf(((sf[nf][2] + mk0) + mq2) - mq2);
            float p3 = __expf(((sf[nf][3] + mk1) + mq2) - mq2);
            l1 += p0 + p1;
            l2 += p2 + p3;
            sf[nf][0] = __uint_as_float(f2tf(p0));
            sf[nf][1] = __uint_as_float(f2tf(p1));
            sf[nf][2] = __uint_as_float(f2tf(p2));
            sf[nf][3] = __uint_as_float(f2tf(p3));
        }

        // ---- O += P @ V : shfl-transpose C-frag -> A-frag ----
#pragma unroll
        for (int kf = 0; kf < 8; kf++) {
            uint32_t c0 = __float_as_uint(sf[kf][0]);
            uint32_t c1 = __float_as_uint(sf[kf][1]);
            uint32_t c2 = __float_as_uint(sf[kf][2]);
            uint32_t c3 = __float_as_uint(sf[kf][3]);
            uint32_t a[4];
            uint32_t x0 = __shfl_sync(0xffffffffu, c0, s1);
            uint32_t x1 = __shfl_sync(0xffffffffu, c1, s1);
            uint32_t y0 = __shfl_sync(0xffffffffu, c2, s1);
            uint32_t y1 = __shfl_sync(0xffffffffu, c3, s1);
            a[0] = odd ? x1 : x0;
            a[1] = odd ? y1 : y0;
            x0 = __shfl_sync(0xffffffffu, c0, s2);
            x1 = __shfl_sync(0xffffffffu, c1, s2);
            y0 = __shfl_sync(0xffffffffu, c2, s2);
            y1 = __shfl_sync(0xffffffffu, c3, s2);
            a[2] = odd ? x1 : x0;
            a[3] = odd ? y1 : y0;
#pragma unroll
            for (int nf = 0; nf < 8; nf++) {
                uint32_t vb[2];
                vb[0] = __float_as_uint(*AVS(cur, kf * 8 + t4, nf * 8 + gid));
                vb[1] = __float_as_uint(*AVS(cur, kf * 8 + t4 + 4, nf * 8 + gid));
                mma_tf32(acc[nf], a, vb);
            }
        }
        __syncthreads();  // all warps done with buf[cur] before it is refilled
    }

    // reduce l across the quad (4 t4 lanes cover each row)
    l1 += __shfl_xor_sync(0xffffffffu, l1, 1);
    l1 += __shfl_xor_sync(0xffffffffu, l1, 2);
    l2 += __shfl_xor_sync(0xffffffffu, l2, 1);
    l2 += __shfl_xor_sync(0xffffffffu, l2, 2);

    // epilogue: normalize + write ctx (B,S,H*64)
    const float i1 = 1.0f / l1, i2 = 1.0f / l2;
    const int row1 = q0 + warp * 16 + gid;
    float* o1 = ctx + ((size_t)(b * SS + row1)) * DD + h * 64;
    float* o2 = o1 + 8 * DD;
#pragma unroll
    for (int nf = 0; nf < 8; nf++) {
        *reinterpret_cast<float2*>(&o1[nf * 8 + t4 * 2]) =
            make_float2(acc[nf][0] * i1, acc[nf][1] * i1);
        *reinterpret_cast<float2*>(&o2[nf * 8 + t4 * 2]) =
            make_float2(acc[nf][2] * i2, acc[nf][3] * i2);
    }
}

// ---------------- launch ----------------
extern "C" void kernel_launch(void* const* d_in, const int* in_sizes, int n_in,
                              void* d_out, int out_size)
{
    (void)in_sizes; (void)n_in; (void)out_size;
    const float* query = (const float*)d_in[0];
    const float* value = (const float*)d_in[1];
    const int*   amask = (const int*)d_in[2];
    const float* Wq = (const float*)d_in[3];
    const float* bq = (const float*)d_in[4];
    const float* Wk = (const float*)d_in[5];
    const float* bk = (const float*)d_in[6];
    const float* Wv = (const float*)d_in[7];
    const float* bv = (const float*)d_in[8];
    const float* Wo = (const float*)d_in[9];
    const float* bo = (const float*)d_in[10];
    float* out = (float*)d_out;

    float *pq, *pk, *pv, *pctx;
    cudaGetSymbolAddress((void**)&pq, g_q);
    cudaGetSymbolAddress((void**)&pk, g_k);
    cudaGetSymbolAddress((void**)&pv, g_v);
    cudaGetSymbolAddress((void**)&pctx, g_ctx);

    const int M = BB * SS;              // 8192
    const dim3 ggrid(DD / 64, M / 128); // (8, 64)

    gemm_tc<1><<<ggrid, 256>>>(query, Wq, bq, pq, M, DD, DD, 0.125f);  // Q (pre-scaled)
    gemm_tc<1><<<ggrid, 256>>>(value, Wk, bk, pk, M, DD, DD, 1.0f);    // K
    gemm_tc<1><<<ggrid, 256>>>(value, Wv, bv, pv, M, DD, DD, 1.0f);    // V

    const int smem = SMEM_FLOATS * 4;   // ~72.2 KB
    cudaFuncSetAttribute(attn_hmma, cudaFuncAttributeMaxDynamicSharedMemorySize, smem);
    attn_hmma<<<dim3(SS / 64, BB * HH), 128, smem>>>(pq, pk, pv, amask, pctx);

    gemm_tc<0><<<ggrid, 256>>>(pctx, Wo, bo, out, M, DD, DD, 1.0f);    // out proj
}

// round 7
// speedup vs baseline: 2.2198x; 1.5124x over previous
#include <cuda_runtime.h>
#include <cuda_fp16.h>
#include <stdint.h>
#include <math.h>

#define BB 4
#define SS 2048
#define DD 512
#define HH 8

// ---------------- scratch (allocation-free: __device__ globals) ----------------
__device__ __half g_q[BB * HH * SS * 64];   // (B,H,S,64) fp16, pre-scaled by 0.125
__device__ __half g_k[BB * HH * SS * 64];   // (B,H,S,64) fp16
__device__ __half g_v[BB * HH * SS * 64];   // (B,H,S,64) fp16
__device__ float  g_ctx[BB * SS * DD];      // (B,S,512)

// ---------------- helpers ----------------
__device__ __forceinline__ uint32_t f2tf(float x) {
    uint32_t r;
    asm("cvt.rna.tf32.f32 %0, %1;" : "=r"(r) : "f"(x));
    return r;
}

__device__ __forceinline__ void mma_tf32(float* c, const uint32_t* a, const uint32_t* b) {
    asm volatile(
        "mma.sync.aligned.m16n8k8.row.col.f32.tf32.tf32.f32 "
        "{%0,%1,%2,%3}, {%4,%5,%6,%7}, {%8,%9}, {%0,%1,%2,%3};\n"
        : "+f"(c[0]), "+f"(c[1]), "+f"(c[2]), "+f"(c[3])
        : "r"(a[0]), "r"(a[1]), "r"(a[2]), "r"(a[3]), "r"(b[0]), "r"(b[1]));
}

__device__ __forceinline__ void mma_f16(float* c, const uint32_t* a, const uint32_t* b) {
    asm volatile(
        "mma.sync.aligned.m16n8k16.row.col.f32.f16.f16.f32 "
        "{%0,%1,%2,%3}, {%4,%5,%6,%7}, {%8,%9}, {%0,%1,%2,%3};\n"
        : "+f"(c[0]), "+f"(c[1]), "+f"(c[2]), "+f"(c[3])
        : "r"(a[0]), "r"(a[1]), "r"(a[2]), "r"(a[3]), "r"(b[0]), "r"(b[1]));
}

__device__ __forceinline__ void ldm4(uint32_t* r, uint32_t addr) {
    asm volatile("ldmatrix.sync.aligned.m8n8.x4.shared.b16 {%0,%1,%2,%3}, [%4];"
                 : "=r"(r[0]), "=r"(r[1]), "=r"(r[2]), "=r"(r[3]) : "r"(addr));
}
__device__ __forceinline__ void ldm4t(uint32_t* r, uint32_t addr) {
    asm volatile("ldmatrix.sync.aligned.m8n8.x4.trans.shared.b16 {%0,%1,%2,%3}, [%4];"
                 : "=r"(r[0]), "=r"(r[1]), "=r"(r[2]), "=r"(r[3]) : "r"(addr));
}

__device__ __forceinline__ uint32_t smem_u32(const void* p) {
    uint32_t a;
    asm("{ .reg .u64 t; cvta.to.shared.u64 t, %1; cvt.u32.u64 %0, t; }" : "=r"(a) : "l"(p));
    return a;
}
__device__ __forceinline__ void cpa16(uint32_t dst, const void* src) {
    asm volatile("cp.async.cg.shared.global [%0], [%1], 16;" :: "r"(dst), "l"(src));
}
__device__ __forceinline__ uint32_t packh2(float a, float b) {
    __half2 h = __floats2half2_rn(a, b);
    return *reinterpret_cast<uint32_t*>(&h);
}

// ---------------- tensor-core SGEMM (HMMA tf32), proven in R2 ----------------
// MODE 0: plain C[m][n] float. MODE 1: split-head (B,H,S,64) as __half, *scale.
template <int MODE>
__global__ __launch_bounds__(256) void gemm_tc(
    const float* __restrict__ A, const float* __restrict__ W,
    const float* __restrict__ bias, float* __restrict__ C,
    int M, int K, int N, float scale)
{
    __shared__ uint32_t As[16][132];
    __shared__ uint32_t Ws[16][68];

    const int tid = threadIdx.x;
    const int lane = tid & 31, warp = tid >> 5;
    const int gid = lane >> 2, t4 = lane & 3;
    const int wm = warp & 3, wn = warp >> 2;
    const int m0 = blockIdx.y * 128, n0 = blockIdx.x * 64;

    const int ar = tid >> 1, ac = (tid & 1) * 8;
    const int br = tid >> 4, bc = (tid & 15) * 4;

    const float* Aptr = A + (size_t)(m0 + ar) * K + ac;
    const float* Wptr = W + (size_t)br * N + n0 + bc;

    float acc[2][4][4];
#pragma unroll
    for (int i = 0; i < 2; i++)
#pragma unroll
        for (int j = 0; j < 4; j++)
#pragma unroll
            for (int k = 0; k < 4; k++) acc[i][j][k] = 0.0f;

    float4 apre0 = *reinterpret_cast<const float4*>(Aptr);
    float4 apre1 = *reinterpret_cast<const float4*>(Aptr + 4);
    float4 wpre  = *reinterpret_cast<const float4*>(Wptr);

    for (int k0 = 0; k0 < K; k0 += 16) {
        As[ac + 0][ar] = f2tf(apre0.x);
        As[ac + 1][ar] = f2tf(apre0.y);
        As[ac + 2][ar] = f2tf(apre0.z);
        As[ac + 3][ar] = f2tf(apre0.w);
        As[ac + 4][ar] = f2tf(apre1.x);
        As[ac + 5][ar] = f2tf(apre1.y);
        As[ac + 6][ar] = f2tf(apre1.z);
        As[ac + 7][ar] = f2tf(apre1.w);
        Ws[br][bc + 0] = f2tf(wpre.x);
        Ws[br][bc + 1] = f2tf(wpre.y);
        Ws[br][bc + 2] = f2tf(wpre.z);
        Ws[br][bc + 3] = f2tf(wpre.w);
        __syncthreads();

        if (k0 + 16 < K) {
            apre0 = *reinterpret_cast<const float4*>(Aptr + k0 + 16);
            apre1 = *reinterpret_cast<const float4*>(Aptr + k0 + 20);
            wpre  = *reinterpret_cast<const float4*>(Wptr + (size_t)(k0 + 16) * N);
        }

#pragma unroll
        for (int ks = 0; ks < 2; ks++) {
            const int kk = ks * 8;
            uint32_t af[2][4], bf[4][2];
#pragma unroll
            for (int mf = 0; mf < 2; mf++) {
                const int mr = wm * 32 + mf * 16 + gid;
                af[mf][0] = As[kk + t4][mr];
                af[mf][1] = As[kk + t4][mr + 8];
                af[mf][2] = As[kk + t4 + 4][mr];
                af[mf][3] = As[kk + t4 + 4][mr + 8];
            }
#pragma unroll
            for (int nf = 0; nf < 4; nf++) {
                const int nc = wn * 32 + nf * 8 + gid;
                bf[nf][0] = Ws[kk + t4][nc];
                bf[nf][1] = Ws[kk + t4 + 4][nc];
            }
#pragma unroll
            for (int mf = 0; mf < 2; mf++)
#pragma unroll
                for (int nf = 0; nf < 4; nf++)
                    mma_tf32(acc[mf][nf], af[mf], bf[nf]);
        }
        __syncthreads();
    }

#pragma unroll
    for (int mf = 0; mf < 2; mf++) {
#pragma unroll
        for (int half = 0; half < 2; half++) {
            const int m = m0 + wm * 32 + mf * 16 + gid + half * 8;
#pragma unroll
            for (int nf = 0; nf < 4; nf++) {
                const int n = n0 + wn * 32 + nf * 8 + t4 * 2;
                float vx = acc[mf][nf][half * 2 + 0] + bias[n];
                float vy = acc[mf][nf][half * 2 + 1] + bias[n + 1];
                if (MODE == 0) {
                    *reinterpret_cast<float2*>(&C[(size_t)m * N + n]) =
                        make_float2(vx, vy);
                } else {
                    const int b = m >> 11, s = m & 2047;
                    const int h = n >> 6, d = n & 63;
                    __half* Ch = reinterpret_cast<__half*>(C);
                    __half2 hv = __floats2half2_rn(vx * scale, vy * scale);
                    *reinterpret_cast<__half2*>(
                        &Ch[(((size_t)(b * HH + h)) * SS + s) * 64 + d]) = hv;
                }
            }
        }
    }
}

// ---------------- fp16 HMMA flash attention ----------------
// 128 threads (4 warps), 64 queries, 16 rows/warp, 32 key tiles of 64.
// K/V staged [key][d] fp16, rows padded to 144B. QK B-frags: ldmatrix (no trans);
// PV B-frags: ldmatrix.trans (same layout!). P: C-frag -> A-frag by half2 pack
// (zero shuffles). Fixed-shift softmax (no online max / rescale), fp32 l & O.
#define TILEB 9216                     // 64 rows * 144 B
#define SMKO(buf)  ((buf) * TILEB)
#define SMVO(buf)  (2 * TILEB + (buf) * TILEB)
#define SMMKO(buf) (4 * TILEB + (buf) * 256)
#define SMEM_B     (4 * TILEB + 512)
#define NT (SS / 64)

__global__ __launch_bounds__(128, 4) void attn_hmma(
    const __half* __restrict__ Q, const __half* __restrict__ K,
    const __half* __restrict__ V, const int* __restrict__ mask,
    float* __restrict__ ctx)
{
    extern __shared__ char smc[];
    const uint32_t smb = smem_u32(smc);

    const int tid = threadIdx.x;
    const int lane = tid & 31, warp = tid >> 5;
    const int gid = lane >> 2, t4 = lane & 3;
    const int bh = blockIdx.y, b = bh >> 3, h = bh & 7;
    const int q0 = blockIdx.x * 64;

    const __half* Qb = Q + (size_t)bh * SS * 64;
    const __half* Kb = K + (size_t)bh * SS * 64;
    const __half* Vb = V + (size_t)bh * SS * 64;
    const int* mrow = mask + b * SS;

    // Q a-fragments (m16n8k16): 4 k-blocks of 16
    uint32_t qa[4][4];
    {
        const __half* q1 = Qb + (size_t)(q0 + warp * 16 + gid) * 64;
        const __half* q2 = q1 + 8 * 64;
#pragma unroll
        for (int kf = 0; kf < 4; kf++) {
            qa[kf][0] = *reinterpret_cast<const uint32_t*>(q1 + kf * 16 + 2 * t4);
            qa[kf][1] = *reinterpret_cast<const uint32_t*>(q2 + kf * 16 + 2 * t4);
            qa[kf][2] = *reinterpret_cast<const uint32_t*>(q1 + kf * 16 + 8 + 2 * t4);
            qa[kf][3] = *reinterpret_cast<const uint32_t*>(q2 + kf * 16 + 8 + 2 * t4);
        }
    }
    const float mq1 = mrow[q0 + warp * 16 + gid] ? 0.0f : -1e9f;
    const float mq2 = mrow[q0 + warp * 16 + gid + 8] ? 0.0f : -1e9f;

    float acc[8][4];
#pragma unroll
    for (int nf = 0; nf < 8; nf++)
#pragma unroll
        for (int e = 0; e < 4; e++) acc[nf][e] = 0.0f;
    float l1 = 0.0f, l2 = 0.0f;

    // cp.async fill: row = tid>>1 (0..63), 4 of 8 16B chunks per half of row
    const int fr = tid >> 1, c0 = (tid & 1) * 4;

    // ldmatrix per-lane row offsets (shared by K and V address formulas)
    const int lr = lane & 7, lg1 = (lane >> 3) & 1, lg2 = (lane >> 4) & 1;
    const uint32_t krow = (uint32_t)((lg2 * 8 + lr) * 144 + lg1 * 16);
    const uint32_t vrow = (uint32_t)((lg1 * 8 + lr) * 144 + lg2 * 16);

    // prologue: tile 0 -> buf 0
    {
        const __half* kp = Kb + (size_t)fr * 64 + c0 * 8;
        const __half* vp = Vb + (size_t)fr * 64 + c0 * 8;
#pragma unroll
        for (int i = 0; i < 4; i++) {
            cpa16(smb + SMKO(0) + (uint32_t)(fr * 144 + (c0 + i) * 16), kp + i * 8);
            cpa16(smb + SMVO(0) + (uint32_t)(fr * 144 + (c0 + i) * 16), vp + i * 8);
        }
        asm volatile("cp.async.commit_group;");
        if (tid < 64)
            *reinterpret_cast<float*>(smc + SMMKO(0) + tid * 4) =
                mrow[tid] ? 0.0f : -1e9f;
    }

    for (int t = 0; t < NT; t++) {
        const int cur = t & 1;
        if (t + 1 < NT) {
            const int nxt = cur ^ 1, k1 = (t + 1) * 64;
            const __half* kp = Kb + (size_t)(k1 + fr) * 64 + c0 * 8;
            const __half* vp = Vb + (size_t)(k1 + fr) * 64 + c0 * 8;
#pragma unroll
            for (int i = 0; i < 4; i++) {
                cpa16(smb + SMKO(nxt) + (uint32_t)(fr * 144 + (c0 + i) * 16), kp + i * 8);
                cpa16(smb + SMVO(nxt) + (uint32_t)(fr * 144 + (c0 + i) * 16), vp + i * 8);
            }
            asm volatile("cp.async.commit_group;");
            if (tid < 64)
                *reinterpret_cast<float*>(smc + SMMKO(nxt) + tid * 4) =
                    mrow[k1 + tid] ? 0.0f : -1e9f;
            asm volatile("cp.async.wait_group 1;");
        } else {
            asm volatile("cp.async.wait_group 0;");
        }
        __syncthreads();

        const uint32_t kbase = smb + SMKO(cur) + krow;
        const uint32_t vbase = smb + SMVO(cur) + vrow;
        const float* mkf = reinterpret_cast<const float*>(smc + SMMKO(cur));

        // ---- S = Q @ K^T : 16x64 per warp ----
        float sf[8][4];
#pragma unroll
        for (int nf = 0; nf < 8; nf++)
#pragma unroll
            for (int e = 0; e < 4; e++) sf[nf][e] = 0.0f;
#pragma unroll
        for (int kf = 0; kf < 4; kf++) {
#pragma unroll
            for (int nfp = 0; nfp < 4; nfp++) {
                uint32_t kb[4];
                ldm4(kb, kbase + nfp * 2304 + kf * 32);
                mma_f16(sf[2 * nfp], qa[kf], kb);
                mma_f16(sf[2 * nfp + 1], qa[kf], kb + 2);
            }
        }

        // ---- masked softmax, fixed shift (ref fp32 absorption preserved) ----
#pragma unroll
        for (int nf = 0; nf < 8; nf++) {
            const float mk0 = mkf[nf * 8 + t4 * 2];
            const float mk1 = mkf[nf * 8 + t4 * 2 + 1];
            float p0 = __expf(((sf[nf][0] + mk0) + mq1) - mq1);
            float p1 = __expf(((sf[nf][1] + mk1) + mq1) - mq1);
            float p2 = __expf(((sf[nf][2] + mk0) + mq2) - mq2);
            float p3 = __expf(((sf[nf][3] + mk1) + mq2) - mq2);
            l1 += p0 + p1;
            l2 += p2 + p3;
            sf[nf][0] = p0; sf[nf][1] = p1; sf[nf][2] = p2; sf[nf][3] = p3;
        }

        // ---- pack P C-frags into fp16 A-frags (no transpose needed) ----
        uint32_t pa[4][4];
#pragma unroll
        for (int kf = 0; kf < 4; kf++) {
            pa[kf][0] = packh2(sf[2 * kf][0], sf[2 * kf][1]);
            pa[kf][1] = packh2(sf[2 * kf][2], sf[2 * kf][3]);
            pa[kf][2] = packh2(sf[2 * kf + 1][0], sf[2 * kf + 1][1]);
            pa[kf][3] = packh2(sf[2 * kf + 1][2], sf[2 * kf + 1][3]);
        }

        // ---- O += P @ V : B-frags via ldmatrix.trans from [key][d] ----
#pragma unroll
        for (int kf = 0; kf < 4; kf++) {
#pragma unroll
            for (int nfp = 0; nfp < 4; nfp++) {
                uint32_t vb[4];
                ldm4t(vb, vbase + kf * 2304 + nfp * 32);
                mma_f16(acc[2 * nfp], pa[kf], vb);
                mma_f16(acc[2 * nfp + 1], pa[kf], vb + 2);
            }
        }
        __syncthreads();  // all warps done with buf[cur] before refill
    }

    // reduce l across the quad (4 t4 lanes cover each row)
    l1 += __shfl_xor_sync(0xffffffffu, l1, 1);
    l1 += __shfl_xor_sync(0xffffffffu, l1, 2);
    l2 += __shfl_xor_sync(0xffffffffu, l2, 1);
    l2 += __shfl_xor_sync(0xffffffffu, l2, 2);

    // epilogue: normalize + write ctx (B,S,H*64)
    const float i1 = 1.0f / l1, i2 = 1.0f / l2;
    const int row1 = q0 + warp * 16 + gid;
    float* o1 = ctx + ((size_t)(b * SS + row1)) * DD + h * 64;
    float* o2 = o1 + 8 * DD;
#pragma unroll
    for (int nf = 0; nf < 8; nf++) {
        *reinterpret_cast<float2*>(&o1[nf * 8 + t4 * 2]) =
            make_float2(acc[nf][0] * i1, acc[nf][1] * i1);
        *reinterpret_cast<float2*>(&o2[nf * 8 + t4 * 2]) =
            make_float2(acc[nf][2] * i2, acc[nf][3] * i2);
    }
}

// ---------------- launch ----------------
extern "C" void kernel_launch(void* const* d_in, const int* in_sizes, int n_in,
                              void* d_out, int out_size)
{
    (void)in_sizes; (void)n_in; (void)out_size;
    const float* query = (const float*)d_in[0];
    const float* value = (const float*)d_in[1];
    const int*   amask = (const int*)d_in[2];
    const float* Wq = (const float*)d_in[3];
    const float* bq = (const float*)d_in[4];
    const float* Wk = (const float*)d_in[5];
    const float* bk = (const float*)d_in[6];
    const float* Wv = (const float*)d_in[7];
    const float* bv = (const float*)d_in[8];
    const float* Wo = (const float*)d_in[9];
    const float* bo = (const float*)d_in[10];
    float* out = (float*)d_out;

    __half *pq, *pk, *pv;
    float *pctx;
    cudaGetSymbolAddress((void**)&pq, g_q);
    cudaGetSymbolAddress((void**)&pk, g_k);
    cudaGetSymbolAddress((void**)&pv, g_v);
    cudaGetSymbolAddress((void**)&pctx, g_ctx);

    const int M = BB * SS;              // 8192
    const dim3 ggrid(DD / 64, M / 128); // (8, 64)

    gemm_tc<1><<<ggrid, 256>>>(query, Wq, bq, (float*)pq, M, DD, DD, 0.125f);
    gemm_tc<1><<<ggrid, 256>>>(value, Wk, bk, (float*)pk, M, DD, DD, 1.0f);
    gemm_tc<1><<<ggrid, 256>>>(value, Wv, bv, (float*)pv, M, DD, DD, 1.0f);

    cudaFuncSetAttribute(attn_hmma, cudaFuncAttributeMaxDynamicSharedMemorySize, SMEM_B);
    attn_hmma<<<dim3(SS / 64, BB * HH), 128, SMEM_B>>>(pq, pk, pv, amask, pctx);

    gemm_tc<0><<<ggrid, 256>>>(pctx, Wo, bo, out, M, DD, DD, 1.0f);
}

// round 8
// speedup vs baseline: 3.8592x; 1.7385x over previous
#include <cuda_runtime.h>
#include <cuda_fp16.h>
#include <stdint.h>
#include <math.h>

#define BB 4
#define SS 2048
#define DD 512
#define HH 8

// ---------------- scratch (allocation-free: __device__ globals) ----------------
__device__ __half g_hquery[BB * SS * DD];   // fp16 copy of query
__device__ __half g_hvalue[BB * SS * DD];   // fp16 copy of value
__device__ __half g_hW[4][DD * DD];         // fp16 copies of Wq,Wk,Wv,Wo
__device__ __half g_q[BB * HH * SS * 64];   // (B,H,S,64) fp16, pre-scaled by 0.125
__device__ __half g_k[BB * HH * SS * 64];
__device__ __half g_v[BB * HH * SS * 64];
__device__ __half g_ctx[BB * SS * DD];      // (B,S,512) fp16

// ---------------- helpers ----------------
__device__ __forceinline__ void mma_f16(float* c, const uint32_t* a, const uint32_t* b) {
    asm volatile(
        "mma.sync.aligned.m16n8k16.row.col.f32.f16.f16.f32 "
        "{%0,%1,%2,%3}, {%4,%5,%6,%7}, {%8,%9}, {%0,%1,%2,%3};\n"
        : "+f"(c[0]), "+f"(c[1]), "+f"(c[2]), "+f"(c[3])
        : "r"(a[0]), "r"(a[1]), "r"(a[2]), "r"(a[3]), "r"(b[0]), "r"(b[1]));
}
__device__ __forceinline__ void ldm4(uint32_t* r, uint32_t addr) {
    asm volatile("ldmatrix.sync.aligned.m8n8.x4.shared.b16 {%0,%1,%2,%3}, [%4];"
                 : "=r"(r[0]), "=r"(r[1]), "=r"(r[2]), "=r"(r[3]) : "r"(addr));
}
__device__ __forceinline__ void ldm4t(uint32_t* r, uint32_t addr) {
    asm volatile("ldmatrix.sync.aligned.m8n8.x4.trans.shared.b16 {%0,%1,%2,%3}, [%4];"
                 : "=r"(r[0]), "=r"(r[1]), "=r"(r[2]), "=r"(r[3]) : "r"(addr));
}
__device__ __forceinline__ uint32_t smem_u32(const void* p) {
    uint32_t a;
    asm("{ .reg .u64 t; cvta.to.shared.u64 t, %1; cvt.u32.u64 %0, t; }" : "=r"(a) : "l"(p));
    return a;
}
__device__ __forceinline__ void cpa16(uint32_t dst, const void* src) {
    asm volatile("cp.async.cg.shared.global [%0], [%1], 16;" :: "r"(dst), "l"(src));
}
__device__ __forceinline__ uint32_t packh2(float a, float b) {
    __half2 h = __floats2half2_rn(a, b);
    return *reinterpret_cast<uint32_t*>(&h);
}

// ---------------- fp32 -> fp16 convert (vectorized) ----------------
__global__ void cvt_h(const float* __restrict__ src, __half* __restrict__ dst, int n4) {
    const int i = blockIdx.x * blockDim.x + threadIdx.x;
    if (i < n4) {
        float4 v = reinterpret_cast<const float4*>(src)[i];
        __half2 h0 = __floats2half2_rn(v.x, v.y);
        __half2 h1 = __floats2half2_rn(v.z, v.w);
        reinterpret_cast<__half2*>(dst)[i * 2] = h0;
        reinterpret_cast<__half2*>(dst)[i * 2 + 1] = h1;
    }
}

// ---------------- fp16 HMMA GEMM: C = A[M,K] @ W[K,N] + bias ----------------
// CTA tile 128x128, BK=32, 256 threads = 8 warps (4m x 2n), warp tile 32x64.
// cp.async 2-stage, ldmatrix fragments. K,N,M multiples of 32/128. A,W fp16.
// MODE 0: C fp32 [M][N] (+bias). MODE 1: C fp16 split-head (B,H,S,64), *scale (+bias).
#define APITCH 80     // bytes per A row (32 fp16 + pad)
#define BPITCH 272    // bytes per B row (128 fp16 + pad)
#define ASTG (128 * APITCH)           // 10240
#define BSTG (32 * BPITCH)            // 8704
#define STG  (ASTG + BSTG)            // 18944

template <int MODE>
__global__ __launch_bounds__(256) void gemm_h(
    const __half* __restrict__ A, const __half* __restrict__ W,
    const float* __restrict__ bias, void* __restrict__ Cv,
    int M, int K, int N, float scale)
{
    __shared__ char sm[2 * STG];
    const uint32_t smb = smem_u32(sm);

    const int tid = threadIdx.x;
    const int lane = tid & 31, warp = tid >> 5;
    const int gid = lane >> 2, t4 = lane & 3;
    const int wm = warp & 3, wn = warp >> 2;
    const int m0 = blockIdx.y * 128, n0 = blockIdx.x * 128;

    // cp.async assignments
    const int arow = tid >> 1, ahalf = tid & 1;          // A: 128 rows x 2 halves(32B)
    const int brow = tid >> 4, bcol = tid & 15;          // B: 16 row-pairs x 16 chunks

    const __half* Ap = A + (size_t)(m0 + arow) * K + ahalf * 16;
    const __half* Wp = W + (size_t)brow * N + n0 + bcol * 8;

    float acc[2][8][4];
#pragma unroll
    for (int i = 0; i < 2; i++)
#pragma unroll
        for (int j = 0; j < 8; j++)
#pragma unroll
            for (int e = 0; e < 4; e++) acc[i][j][e] = 0.0f;

    // ldmatrix lane addressing
    const uint32_t a_l = (uint32_t)((lane & 15) * APITCH + (lane >> 4) * 16);
    const uint32_t b_l = (uint32_t)(((lane & 7) + ((lane >> 3) & 1) * 8) * BPITCH +
                                    ((lane >> 4) & 1) * 16);

    const int NITER = K / 32;

    // prologue: stage 0
    {
        const uint32_t da = smb + (uint32_t)(arow * APITCH + ahalf * 32);
        cpa16(da, Ap);
        cpa16(da + 16, Ap + 8);
        const uint32_t db = smb + (uint32_t)(ASTG + brow * BPITCH + bcol * 16);
        cpa16(db, Wp);
        cpa16(db + 16 * BPITCH, Wp + (size_t)16 * N);
        asm volatile("cp.async.commit_group;");
    }

    for (int it = 0; it < NITER; it++) {
        const int cur = it & 1;
        if (it + 1 < NITER) {
            const int nxt = cur ^ 1, k1 = (it + 1) * 32;
            const uint32_t da = smb + (uint32_t)(nxt * STG + arow * APITCH + ahalf * 32);
            cpa16(da, Ap + k1);
            cpa16(da + 16, Ap + k1 + 8);
            const uint32_t db = smb + (uint32_t)(nxt * STG + ASTG + brow * BPITCH + bcol * 16);
            cpa16(db, Wp + (size_t)k1 * N);
            cpa16(db + 16 * BPITCH, Wp + (size_t)(k1 + 16) * N);
            asm volatile("cp.async.commit_group;");
            asm volatile("cp.async.wait_group 1;");
        } else {
            asm volatile("cp.async.wait_group 0;");
        }
        __syncthreads();

        const uint32_t abase = smb + (uint32_t)(cur * STG) + a_l;
        const uint32_t bbase = smb + (uint32_t)(cur * STG + ASTG) + b_l;

        uint32_t af[2][2][4];
#pragma unroll
        for (int mb = 0; mb < 2; mb++)
#pragma unroll
            for (int kb = 0; kb < 2; kb++)
                ldm4(af[mb][kb], abase + (uint32_t)((wm * 32 + mb * 16) * APITCH + kb * 32));

#pragma unroll
        for (int kb = 0; kb < 2; kb++) {
#pragma unroll
            for (int nb = 0; nb < 4; nb++) {
                uint32_t bf[4];
                ldm4t(bf, bbase + (uint32_t)(kb * 16 * BPITCH + wn * 128 + nb * 32));
#pragma unroll
                for (int mb = 0; mb < 2; mb++) {
                    mma_f16(acc[mb][2 * nb], af[mb][kb], bf);
                    mma_f16(acc[mb][2 * nb + 1], af[mb][kb], bf + 2);
                }
            }
        }
        __syncthreads();
    }

    // epilogue
#pragma unroll
    for (int mb = 0; mb < 2; mb++) {
#pragma unroll
        for (int half = 0; half < 2; half++) {
            const int m = m0 + wm * 32 + mb * 16 + gid + half * 8;
#pragma unroll
            for (int nf = 0; nf < 8; nf++) {
                const int n = n0 + wn * 64 + nf * 8 + t4 * 2;
                float vx = acc[mb][nf][half * 2 + 0] + bias[n];
                float vy = acc[mb][nf][half * 2 + 1] + bias[n + 1];
                if (MODE == 0) {
                    float* C = reinterpret_cast<float*>(Cv);
                    *reinterpret_cast<float2*>(&C[(size_t)m * N + n]) =
                        make_float2(vx, vy);
                } else {
                    const int b = m >> 11, s = m & 2047;
                    const int h = n >> 6, d = n & 63;
                    __half* C = reinterpret_cast<__half*>(Cv);
                    __half2 hv = __floats2half2_rn(vx * scale, vy * scale);
                    *reinterpret_cast<__half2*>(
                        &C[(((size_t)(b * HH + h)) * SS + s) * 64 + d]) = hv;
                }
            }
        }
    }
}

// ---------------- fp16 HMMA flash attention (proven R6; fp16 ctx out) ----------------
#define TILEB 9216                     // 64 rows * 144 B
#define SMKO(buf)  ((buf) * TILEB)
#define SMVO(buf)  (2 * TILEB + (buf) * TILEB)
#define SMMKO(buf) (4 * TILEB + (buf) * 256)
#define SMEM_B     (4 * TILEB + 512)
#define NT (SS / 64)

__global__ __launch_bounds__(128, 4) void attn_hmma(
    const __half* __restrict__ Q, const __half* __restrict__ K,
    const __half* __restrict__ V, const int* __restrict__ mask,
    __half* __restrict__ ctx)
{
    extern __shared__ char smc[];
    const uint32_t smb = smem_u32(smc);

    const int tid = threadIdx.x;
    const int lane = tid & 31, warp = tid >> 5;
    const int gid = lane >> 2, t4 = lane & 3;
    const int bh = blockIdx.y, b = bh >> 3, h = bh & 7;
    const int q0 = blockIdx.x * 64;

    const __half* Qb = Q + (size_t)bh * SS * 64;
    const __half* Kb = K + (size_t)bh * SS * 64;
    const __half* Vb = V + (size_t)bh * SS * 64;
    const int* mrow = mask + b * SS;

    uint32_t qa[4][4];
    {
        const __half* q1 = Qb + (size_t)(q0 + warp * 16 + gid) * 64;
        const __half* q2 = q1 + 8 * 64;
#pragma unroll
        for (int kf = 0; kf < 4; kf++) {
            qa[kf][0] = *reinterpret_cast<const uint32_t*>(q1 + kf * 16 + 2 * t4);
            qa[kf][1] = *reinterpret_cast<const uint32_t*>(q2 + kf * 16 + 2 * t4);
            qa[kf][2] = *reinterpret_cast<const uint32_t*>(q1 + kf * 16 + 8 + 2 * t4);
            qa[kf][3] = *reinterpret_cast<const uint32_t*>(q2 + kf * 16 + 8 + 2 * t4);
        }
    }
    const float mq1 = mrow[q0 + warp * 16 + gid] ? 0.0f : -1e9f;
    const float mq2 = mrow[q0 + warp * 16 + gid + 8] ? 0.0f : -1e9f;

    float acc[8][4];
#pragma unroll
    for (int nf = 0; nf < 8; nf++)
#pragma unroll
        for (int e = 0; e < 4; e++) acc[nf][e] = 0.0f;
    float l1 = 0.0f, l2 = 0.0f;

    const int fr = tid >> 1, c0 = (tid & 1) * 4;
    const int lr = lane & 7, lg1 = (lane >> 3) & 1, lg2 = (lane >> 4) & 1;
    const uint32_t krow = (uint32_t)((lg2 * 8 + lr) * 144 + lg1 * 16);
    const uint32_t vrow = (uint32_t)((lg1 * 8 + lr) * 144 + lg2 * 16);

    {
        const __half* kp = Kb + (size_t)fr * 64 + c0 * 8;
        const __half* vp = Vb + (size_t)fr * 64 + c0 * 8;
#pragma unroll
        for (int i = 0; i < 4; i++) {
            cpa16(smb + SMKO(0) + (uint32_t)(fr * 144 + (c0 + i) * 16), kp + i * 8);
            cpa16(smb + SMVO(0) + (uint32_t)(fr * 144 + (c0 + i) * 16), vp + i * 8);
        }
        asm volatile("cp.async.commit_group;");
        if (tid < 64)
            *reinterpret_cast<float*>(smc + SMMKO(0) + tid * 4) =
                mrow[tid] ? 0.0f : -1e9f;
    }

    for (int t = 0; t < NT; t++) {
        const int cur = t & 1;
        if (t + 1 < NT) {
            const int nxt = cur ^ 1, k1 = (t + 1) * 64;
            const __half* kp = Kb + (size_t)(k1 + fr) * 64 + c0 * 8;
            const __half* vp = Vb + (size_t)(k1 + fr) * 64 + c0 * 8;
#pragma unroll
            for (int i = 0; i < 4; i++) {
                cpa16(smb + SMKO(nxt) + (uint32_t)(fr * 144 + (c0 + i) * 16), kp + i * 8);
                cpa16(smb + SMVO(nxt) + (uint32_t)(fr * 144 + (c0 + i) * 16), vp + i * 8);
            }
            asm volatile("cp.async.commit_group;");
            if (tid < 64)
                *reinterpret_cast<float*>(smc + SMMKO(nxt) + tid * 4) =
                    mrow[k1 + tid] ? 0.0f : -1e9f;
            asm volatile("cp.async.wait_group 1;");
        } else {
            asm volatile("cp.async.wait_group 0;");
        }
        __syncthreads();

        const uint32_t kbase = smb + SMKO(cur) + krow;
        const uint32_t vbase = smb + SMVO(cur) + vrow;
        const float* mkf = reinterpret_cast<const float*>(smc + SMMKO(cur));

        float sf[8][4];
#pragma unroll
        for (int nf = 0; nf < 8; nf++)
#pragma unroll
            for (int e = 0; e < 4; e++) sf[nf][e] = 0.0f;
#pragma unroll
        for (int kf = 0; kf < 4; kf++) {
#pragma unroll
            for (int nfp = 0; nfp < 4; nfp++) {
                uint32_t kb[4];
                ldm4(kb, kbase + nfp * 2304 + kf * 32);
                mma_f16(sf[2 * nfp], qa[kf], kb);
                mma_f16(sf[2 * nfp + 1], qa[kf], kb + 2);
            }
        }

#pragma unroll
        for (int nf = 0; nf < 8; nf++) {
            const float mk0 = mkf[nf * 8 + t4 * 2];
            const float mk1 = mkf[nf * 8 + t4 * 2 + 1];
            float p0 = __expf(((sf[nf][0] + mk0) + mq1) - mq1);
            float p1 = __expf(((sf[nf][1] + mk1) + mq1) - mq1);
            float p2 = __expf(((sf[nf][2] + mk0) + mq2) - mq2);
            float p3 = __expf(((sf[nf][3] + mk1) + mq2) - mq2);
            l1 += p0 + p1;
            l2 += p2 + p3;
            sf[nf][0] = p0; sf[nf][1] = p1; sf[nf][2] = p2; sf[nf][3] = p3;
        }

        uint32_t pa[4][4];
#pragma unroll
        for (int kf = 0; kf < 4; kf++) {
            pa[kf][0] = packh2(sf[2 * kf][0], sf[2 * kf][1]);
            pa[kf][1] = packh2(sf[2 * kf][2], sf[2 * kf][3]);
            pa[kf][2] = packh2(sf[2 * kf + 1][0], sf[2 * kf + 1][1]);
            pa[kf][3] = packh2(sf[2 * kf + 1][2], sf[2 * kf + 1][3]);
        }

#pragma unroll
        for (int kf = 0; kf < 4; kf++) {
#pragma unroll
            for (int nfp = 0; nfp < 4; nfp++) {
                uint32_t vb[4];
                ldm4t(vb, vbase + kf * 2304 + nfp * 32);
                mma_f16(acc[2 * nfp], pa[kf], vb);
                mma_f16(acc[2 * nfp + 1], pa[kf], vb + 2);
            }
        }
        __syncthreads();
    }

    l1 += __shfl_xor_sync(0xffffffffu, l1, 1);
    l1 += __shfl_xor_sync(0xffffffffu, l1, 2);
    l2 += __shfl_xor_sync(0xffffffffu, l2, 1);
    l2 += __shfl_xor_sync(0xffffffffu, l2, 2);

    const float i1 = 1.0f / l1, i2 = 1.0f / l2;
    const int row1 = q0 + warp * 16 + gid;
    __half* o1 = ctx + ((size_t)(b * SS + row1)) * DD + h * 64;
    __half* o2 = o1 + 8 * DD;
#pragma unroll
    for (int nf = 0; nf < 8; nf++) {
        *reinterpret_cast<__half2*>(&o1[nf * 8 + t4 * 2]) =
            __floats2half2_rn(acc[nf][0] * i1, acc[nf][1] * i1);
        *reinterpret_cast<__half2*>(&o2[nf * 8 + t4 * 2]) =
            __floats2half2_rn(acc[nf][2] * i2, acc[nf][3] * i2);
    }
}

// ---------------- launch ----------------
extern "C" void kernel_launch(void* const* d_in, const int* in_sizes, int n_in,
                              void* d_out, int out_size)
{
    (void)in_sizes; (void)n_in; (void)out_size;
    const float* query = (const float*)d_in[0];
    const float* value = (const float*)d_in[1];
    const int*   amask = (const int*)d_in[2];
    const float* Wq = (const float*)d_in[3];
    const float* bq = (const float*)d_in[4];
    const float* Wk = (const float*)d_in[5];
    const float* bk = (const float*)d_in[6];
    const float* Wv = (const float*)d_in[7];
    const float* bv = (const float*)d_in[8];
    const float* Wo = (const float*)d_in[9];
    const float* bo = (const float*)d_in[10];
    float* out = (float*)d_out;

    __half *hq, *hv, *hW, *pq, *pk, *pv, *pctx;
    cudaGetSymbolAddress((void**)&hq, g_hquery);
    cudaGetSymbolAddress((void**)&hv, g_hvalue);
    cudaGetSymbolAddress((void**)&hW, g_hW);
    cudaGetSymbolAddress((void**)&pq, g_q);
    cudaGetSymbolAddress((void**)&pk, g_k);
    cudaGetSymbolAddress((void**)&pv, g_v);
    cudaGetSymbolAddress((void**)&pctx, g_ctx);

    const int M = BB * SS;               // 8192
    const int NIN = M * DD;              // 4.19M
    const int NW = DD * DD;              // 262144

    // fp32 -> fp16 conversions
    cvt_h<<<(NIN / 4 + 255) / 256, 256>>>(query, hq, NIN / 4);
    cvt_h<<<(NIN / 4 + 255) / 256, 256>>>(value, hv, NIN / 4);
    cvt_h<<<(NW / 4 + 255) / 256, 256>>>(Wq, hW + 0 * (size_t)NW, NW / 4);
    cvt_h<<<(NW / 4 + 255) / 256, 256>>>(Wk, hW + 1 * (size_t)NW, NW / 4);
    cvt_h<<<(NW / 4 + 255) / 256, 256>>>(Wv, hW + 2 * (size_t)NW, NW / 4);
    cvt_h<<<(NW / 4 + 255) / 256, 256>>>(Wo, hW + 3 * (size_t)NW, NW / 4);

    const dim3 ggrid(DD / 128, M / 128); // (4, 64)
    gemm_h<1><<<ggrid, 256>>>(hq, hW + 0 * (size_t)NW, bq, pq, M, DD, DD, 0.125f);
    gemm_h<1><<<ggrid, 256>>>(hv, hW + 1 * (size_t)NW, bk, pk, M, DD, DD, 1.0f);
    gemm_h<1><<<ggrid, 256>>>(hv, hW + 2 * (size_t)NW, bv, pv, M, DD, DD, 1.0f);

    cudaFuncSetAttribute(attn_hmma, cudaFuncAttributeMaxDynamicSharedMemorySize, SMEM_B);
    attn_hmma<<<dim3(SS / 64, BB * HH), 128, SMEM_B>>>(pq, pk, pv, amask, pctx);

    gemm_h<0><<<ggrid, 256>>>(pctx, hW + 3 * (size_t)NW, bo, out, M, DD, DD, 1.0f);
}

// round 9
// speedup vs baseline: 4.0397x; 1.0468x over previous
#include <cuda_runtime.h>
#include <cuda_fp16.h>
#include <stdint.h>
#include <math.h>

#define BB 4
#define SS 2048
#define DD 512
#define HH 8

// ---------------- scratch (allocation-free: __device__ globals) ----------------
__device__ __half g_hquery[BB * SS * DD];   // fp16 copy of query
__device__ __half g_hvalue[BB * SS * DD];   // fp16 copy of value
__device__ __half g_hWq[DD * DD];           // fp16 Wq
__device__ __half g_hWo[DD * DD];           // fp16 Wo
__device__ __half g_hWkv[DD * 2 * DD];      // fp16 [Wk | Wv] concat, row stride 1024
__device__ __half g_q[BB * HH * SS * 64];   // (B,H,S,64) fp16, pre-scaled by 0.125
__device__ __half g_k[BB * HH * SS * 64];
__device__ __half g_v[BB * HH * SS * 64];
__device__ __half g_ctx[BB * SS * DD];      // (B,S,512) fp16

// ---------------- helpers ----------------
__device__ __forceinline__ void mma_f16(float* c, const uint32_t* a, const uint32_t* b) {
    asm volatile(
        "mma.sync.aligned.m16n8k16.row.col.f32.f16.f16.f32 "
        "{%0,%1,%2,%3}, {%4,%5,%6,%7}, {%8,%9}, {%0,%1,%2,%3};\n"
        : "+f"(c[0]), "+f"(c[1]), "+f"(c[2]), "+f"(c[3])
        : "r"(a[0]), "r"(a[1]), "r"(a[2]), "r"(a[3]), "r"(b[0]), "r"(b[1]));
}
__device__ __forceinline__ void ldm4(uint32_t* r, uint32_t addr) {
    asm volatile("ldmatrix.sync.aligned.m8n8.x4.shared.b16 {%0,%1,%2,%3}, [%4];"
                 : "=r"(r[0]), "=r"(r[1]), "=r"(r[2]), "=r"(r[3]) : "r"(addr));
}
__device__ __forceinline__ void ldm4t(uint32_t* r, uint32_t addr) {
    asm volatile("ldmatrix.sync.aligned.m8n8.x4.trans.shared.b16 {%0,%1,%2,%3}, [%4];"
                 : "=r"(r[0]), "=r"(r[1]), "=r"(r[2]), "=r"(r[3]) : "r"(addr));
}
__device__ __forceinline__ uint32_t smem_u32(const void* p) {
    uint32_t a;
    asm("{ .reg .u64 t; cvta.to.shared.u64 t, %1; cvt.u32.u64 %0, t; }" : "=r"(a) : "l"(p));
    return a;
}
__device__ __forceinline__ void cpa16(uint32_t dst, const void* src) {
    asm volatile("cp.async.cg.shared.global [%0], [%1], 16;" :: "r"(dst), "l"(src));
}
__device__ __forceinline__ uint32_t packh2(float a, float b) {
    __half2 h = __floats2half2_rn(a, b);
    return *reinterpret_cast<uint32_t*>(&h);
}

// ---------------- fused fp32 -> fp16 conversions ----------------
// inputs: y==0 -> query, y==1 -> value (NIN/4 float4 each)
__global__ void cvt_in(const float* __restrict__ q, const float* __restrict__ v,
                       __half* __restrict__ dq, __half* __restrict__ dv, int n4) {
    const int i = blockIdx.x * blockDim.x + threadIdx.x;
    const float* src = blockIdx.y ? v : q;
    __half* dst = blockIdx.y ? dv : dq;
    if (i < n4) {
        float4 x = reinterpret_cast<const float4*>(src)[i];
        reinterpret_cast<__half2*>(dst)[i * 2]     = __floats2half2_rn(x.x, x.y);
        reinterpret_cast<__half2*>(dst)[i * 2 + 1] = __floats2half2_rn(x.z, x.w);
    }
}

// weights: y==0 Wq->hWq(stride 512), y==1 Wo->hWo(512), y==2 Wk->hWkv cols 0-511
// (stride 1024), y==3 Wv->hWkv cols 512-1023 (stride 1024). 8 halves per thread.
__global__ void cvt_w(const float* __restrict__ Wq, const float* __restrict__ Wk,
                      const float* __restrict__ Wv, const float* __restrict__ Wo,
                      __half* __restrict__ hWq, __half* __restrict__ hWkv,
                      __half* __restrict__ hWo) {
    const int i = blockIdx.x * blockDim.x + threadIdx.x;   // 0 .. 512*512/8-1
    const int flat = i * 8;
    if (flat >= DD * DD) return;
    const int r = flat >> 9, c = flat & 511;
    const float* src;
    __half* dst;
    switch (blockIdx.y) {
        case 0: src = Wq + flat;          dst = hWq + flat; break;
        case 1: src = Wo + flat;          dst = hWo + flat; break;
        case 2: src = Wk + flat;          dst = hWkv + r * 1024 + c; break;
        default: src = Wv + flat;         dst = hWkv + r * 1024 + 512 + c; break;
    }
    float4 a = reinterpret_cast<const float4*>(src)[0];
    float4 b = reinterpret_cast<const float4*>(src)[1];
    __half2 h[4] = {__floats2half2_rn(a.x, a.y), __floats2half2_rn(a.z, a.w),
                    __floats2half2_rn(b.x, b.y), __floats2half2_rn(b.z, b.w)};
    *reinterpret_cast<uint4*>(dst) = *reinterpret_cast<uint4*>(h);
}

// ---------------- fp16 HMMA GEMM: C = A[M,K] @ W[K,N] + bias ----------------
// CTA tile 128x128, BK=32, 256 threads = 8 warps (4m x 2n), warp tile 32x64.
// MODE 0: C1 fp32 [M][N] (+bias1).
// MODE 1: C1 fp16 split-head (B,H,S,64), *scale (+bias1).           (N=512)
// MODE 2: dual split-head: n<512 -> C1/bias1, else C2/bias2.        (N=1024)
#define APITCH 80
#define BPITCH 272
#define ASTG (128 * APITCH)
#define BSTG (32 * BPITCH)
#define STG  (ASTG + BSTG)

template <int MODE>
__global__ __launch_bounds__(256) void gemm_h(
    const __half* __restrict__ A, const __half* __restrict__ W,
    const float* __restrict__ bias1, const float* __restrict__ bias2,
    void* __restrict__ C1v, void* __restrict__ C2v,
    int M, int K, int N, float scale)
{
    __shared__ char sm[2 * STG];
    const uint32_t smb = smem_u32(sm);

    const int tid = threadIdx.x;
    const int lane = tid & 31, warp = tid >> 5;
    const int gid = lane >> 2, t4 = lane & 3;
    const int wm = warp & 3, wn = warp >> 2;
    const int m0 = blockIdx.y * 128, n0 = blockIdx.x * 128;

    const int arow = tid >> 1, ahalf = tid & 1;
    const int brow = tid >> 4, bcol = tid & 15;

    const __half* Ap = A + (size_t)(m0 + arow) * K + ahalf * 16;
    const __half* Wp = W + (size_t)brow * N + n0 + bcol * 8;

    float acc[2][8][4];
#pragma unroll
    for (int i = 0; i < 2; i++)
#pragma unroll
        for (int j = 0; j < 8; j++)
#pragma unroll
            for (int e = 0; e < 4; e++) acc[i][j][e] = 0.0f;

    const uint32_t a_l = (uint32_t)((lane & 15) * APITCH + (lane >> 4) * 16);
    const uint32_t b_l = (uint32_t)(((lane & 7) + ((lane >> 3) & 1) * 8) * BPITCH +
                                    ((lane >> 4) & 1) * 16);

    const int NITER = K / 32;

    {
        const uint32_t da = smb + (uint32_t)(arow * APITCH + ahalf * 32);
        cpa16(da, Ap);
        cpa16(da + 16, Ap + 8);
        const uint32_t db = smb + (uint32_t)(ASTG + brow * BPITCH + bcol * 16);
        cpa16(db, Wp);
        cpa16(db + 16 * BPITCH, Wp + (size_t)16 * N);
        asm volatile("cp.async.commit_group;");
    }

    for (int it = 0; it < NITER; it++) {
        const int cur = it & 1;
        if (it + 1 < NITER) {
            const int nxt = cur ^ 1, k1 = (it + 1) * 32;
            const uint32_t da = smb + (uint32_t)(nxt * STG + arow * APITCH + ahalf * 32);
            cpa16(da, Ap + k1);
            cpa16(da + 16, Ap + k1 + 8);
            const uint32_t db = smb + (uint32_t)(nxt * STG + ASTG + brow * BPITCH + bcol * 16);
            cpa16(db, Wp + (size_t)k1 * N);
            cpa16(db + 16 * BPITCH, Wp + (size_t)(k1 + 16) * N);
            asm volatile("cp.async.commit_group;");
            asm volatile("cp.async.wait_group 1;");
        } else {
            asm volatile("cp.async.wait_group 0;");
        }
        __syncthreads();

        const uint32_t abase = smb + (uint32_t)(cur * STG) + a_l;
        const uint32_t bbase = smb + (uint32_t)(cur * STG + ASTG) + b_l;

        uint32_t af[2][2][4];
#pragma unroll
        for (int mb = 0; mb < 2; mb++)
#pragma unroll
            for (int kb = 0; kb < 2; kb++)
                ldm4(af[mb][kb], abase + (uint32_t)((wm * 32 + mb * 16) * APITCH + kb * 32));

#pragma unroll
        for (int kb = 0; kb < 2; kb++) {
#pragma unroll
            for (int nb = 0; nb < 4; nb++) {
                uint32_t bf[4];
                ldm4t(bf, bbase + (uint32_t)(kb * 16 * BPITCH + wn * 128 + nb * 32));
#pragma unroll
                for (int mb = 0; mb < 2; mb++) {
                    mma_f16(acc[mb][2 * nb], af[mb][kb], bf);
                    mma_f16(acc[mb][2 * nb + 1], af[mb][kb], bf + 2);
                }
            }
        }
        __syncthreads();
    }

#pragma unroll
    for (int mb = 0; mb < 2; mb++) {
#pragma unroll
        for (int half = 0; half < 2; half++) {
            const int m = m0 + wm * 32 + mb * 16 + gid + half * 8;
#pragma unroll
            for (int nf = 0; nf < 8; nf++) {
                const int n = n0 + wn * 64 + nf * 8 + t4 * 2;
                if (MODE == 0) {
                    float vx = acc[mb][nf][half * 2 + 0] + bias1[n];
                    float vy = acc[mb][nf][half * 2 + 1] + bias1[n + 1];
                    float* C = reinterpret_cast<float*>(C1v);
                    *reinterpret_cast<float2*>(&C[(size_t)m * N + n]) =
                        make_float2(vx, vy);
                } else {
                    const float* bs = (MODE == 2 && n >= 512) ? bias2 - 512 : bias1;
                    __half* C = (MODE == 2 && n >= 512)
                                    ? reinterpret_cast<__half*>(C2v)
                                    : reinterpret_cast<__half*>(C1v);
                    const int nn = (MODE == 2) ? (n & 511) : n;
                    float vx = acc[mb][nf][half * 2 + 0] + bs[n];
                    float vy = acc[mb][nf][half * 2 + 1] + bs[n + 1];
                    const int b = m >> 11, s = m & 2047;
                    const int h = nn >> 6, d = nn & 63;
                    __half2 hv = __floats2half2_rn(vx * scale, vy * scale);
                    *reinterpret_cast<__half2*>(
                        &C[(((size_t)(b * HH + h)) * SS + s) * 64 + d]) = hv;
                }
            }
        }
    }
}

// ---------------- fp16 HMMA flash attention ----------------
// Softmax uses the algebraic form of the ref's fp32 +-1e9 absorption:
// |s| < 32 << ulp(1e9)/2, so p == mk_bit * exp(s * mq_bit) exactly.
#define TILEB 9216
#define SMKO(buf)  ((buf) * TILEB)
#define SMVO(buf)  (2 * TILEB + (buf) * TILEB)
#define SMMKO(buf) (4 * TILEB + (buf) * 256)
#define SMEM_B     (4 * TILEB + 512)
#define NT (SS / 64)

__global__ __launch_bounds__(128, 4) void attn_hmma(
    const __half* __restrict__ Q, const __half* __restrict__ K,
    const __half* __restrict__ V, const int* __restrict__ mask,
    __half* __restrict__ ctx)
{
    extern __shared__ char smc[];
    const uint32_t smb = smem_u32(smc);

    const int tid = threadIdx.x;
    const int lane = tid & 31, warp = tid >> 5;
    const int gid = lane >> 2, t4 = lane & 3;
    const int bh = blockIdx.y, b = bh >> 3, h = bh & 7;
    const int q0 = blockIdx.x * 64;

    const __half* Qb = Q + (size_t)bh * SS * 64;
    const __half* Kb = K + (size_t)bh * SS * 64;
    const __half* Vb = V + (size_t)bh * SS * 64;
    const int* mrow = mask + b * SS;

    uint32_t qa[4][4];
    {
        const __half* q1 = Qb + (size_t)(q0 + warp * 16 + gid) * 64;
        const __half* q2 = q1 + 8 * 64;
#pragma unroll
        for (int kf = 0; kf < 4; kf++) {
            qa[kf][0] = *reinterpret_cast<const uint32_t*>(q1 + kf * 16 + 2 * t4);
            qa[kf][1] = *reinterpret_cast<const uint32_t*>(q2 + kf * 16 + 2 * t4);
            qa[kf][2] = *reinterpret_cast<const uint32_t*>(q1 + kf * 16 + 8 + 2 * t4);
            qa[kf][3] = *reinterpret_cast<const uint32_t*>(q2 + kf * 16 + 8 + 2 * t4);
        }
    }
    const float mq1 = mrow[q0 + warp * 16 + gid] ? 1.0f : 0.0f;      // exp-arg gate
    const float mq2 = mrow[q0 + warp * 16 + gid + 8] ? 1.0f : 0.0f;

    float acc[8][4];
#pragma unroll
    for (int nf = 0; nf < 8; nf++)
#pragma unroll
        for (int e = 0; e < 4; e++) acc[nf][e] = 0.0f;
    float l1 = 0.0f, l2 = 0.0f;

    const int fr = tid >> 1, c0 = (tid & 1) * 4;
    const int lr = lane & 7, lg1 = (lane >> 3) & 1, lg2 = (lane >> 4) & 1;
    const uint32_t krow = (uint32_t)((lg2 * 8 + lr) * 144 + lg1 * 16);
    const uint32_t vrow = (uint32_t)((lg1 * 8 + lr) * 144 + lg2 * 16);

    {
        const __half* kp = Kb + (size_t)fr * 64 + c0 * 8;
        const __half* vp = Vb + (size_t)fr * 64 + c0 * 8;
#pragma unroll
        for (int i = 0; i < 4; i++) {
            cpa16(smb + SMKO(0) + (uint32_t)(fr * 144 + (c0 + i) * 16), kp + i * 8);
            cpa16(smb + SMVO(0) + (uint32_t)(fr * 144 + (c0 + i) * 16), vp + i * 8);
        }
        asm volatile("cp.async.commit_group;");
        if (tid < 64)
            *reinterpret_cast<float*>(smc + SMMKO(0) + tid * 4) =
                mrow[tid] ? 1.0f : 0.0f;                             // multiplicative gate
    }

    for (int t = 0; t < NT; t++) {
        const int cur = t & 1;
        if (t + 1 < NT) {
            const int nxt = cur ^ 1, k1 = (t + 1) * 64;
            const __half* kp = Kb + (size_t)(k1 + fr) * 64 + c0 * 8;
            const __half* vp = Vb + (size_t)(k1 + fr) * 64 + c0 * 8;
#pragma unroll
            for (int i = 0; i < 4; i++) {
                cpa16(smb + SMKO(nxt) + (uint32_t)(fr * 144 + (c0 + i) * 16), kp + i * 8);
                cpa16(smb + SMVO(nxt) + (uint32_t)(fr * 144 + (c0 + i) * 16), vp + i * 8);
            }
            asm volatile("cp.async.commit_group;");
            if (tid < 64)
                *reinterpret_cast<float*>(smc + SMMKO(nxt) + tid * 4) =
                    mrow[k1 + tid] ? 1.0f : 0.0f;
            asm volatile("cp.async.wait_group 1;");
        } else {
            asm volatile("cp.async.wait_group 0;");
        }
        __syncthreads();

        const uint32_t kbase = smb + SMKO(cur) + krow;
        const uint32_t vbase = smb + SMVO(cur) + vrow;
        const float* mkf = reinterpret_cast<const float*>(smc + SMMKO(cur));

        float sf[8][4];
#pragma unroll
        for (int nf = 0; nf < 8; nf++)
#pragma unroll
            for (int e = 0; e < 4; e++) sf[nf][e] = 0.0f;
#pragma unroll
        for (int kf = 0; kf < 4; kf++) {
#pragma unroll
            for (int nfp = 0; nfp < 4; nfp++) {
                uint32_t kb[4];
                ldm4(kb, kbase + nfp * 2304 + kf * 32);
                mma_f16(sf[2 * nfp], qa[kf], kb);
                mma_f16(sf[2 * nfp + 1], qa[kf], kb + 2);
            }
        }

        // p = mk * exp(s * mq)   (exact fp32-absorption equivalent)
#pragma unroll
        for (int nf = 0; nf < 8; nf++) {
            const float mk0 = mkf[nf * 8 + t4 * 2];
            const float mk1 = mkf[nf * 8 + t4 * 2 + 1];
            float p0 = mk0 * __expf(sf[nf][0] * mq1);
            float p1 = mk1 * __expf(sf[nf][1] * mq1);
            float p2 = mk0 * __expf(sf[nf][2] * mq2);
            float p3 = mk1 * __expf(sf[nf][3] * mq2);
            l1 += p0 + p1;
            l2 += p2 + p3;
            sf[nf][0] = p0; sf[nf][1] = p1; sf[nf][2] = p2; sf[nf][3] = p3;
        }

        uint32_t pa[4][4];
#pragma unroll
        for (int kf = 0; kf < 4; kf++) {
            pa[kf][0] = packh2(sf[2 * kf][0], sf[2 * kf][1]);
            pa[kf][1] = packh2(sf[2 * kf][2], sf[2 * kf][3]);
            pa[kf][2] = packh2(sf[2 * kf + 1][0], sf[2 * kf + 1][1]);
            pa[kf][3] = packh2(sf[2 * kf + 1][2], sf[2 * kf + 1][3]);
        }

#pragma unroll
        for (int kf = 0; kf < 4; kf++) {
#pragma unroll
            for (int nfp = 0; nfp < 4; nfp++) {
                uint32_t vb[4];
                ldm4t(vb, vbase + kf * 2304 + nfp * 32);
                mma_f16(acc[2 * nfp], pa[kf], vb);
                mma_f16(acc[2 * nfp + 1], pa[kf], vb + 2);
            }
        }
        __syncthreads();
    }

    l1 += __shfl_xor_sync(0xffffffffu, l1, 1);
    l1 += __shfl_xor_sync(0xffffffffu, l1, 2);
    l2 += __shfl_xor_sync(0xffffffffu, l2, 1);
    l2 += __shfl_xor_sync(0xffffffffu, l2, 2);

    const float i1 = 1.0f / l1, i2 = 1.0f / l2;
    const int row1 = q0 + warp * 16 + gid;
    __half* o1 = ctx + ((size_t)(b * SS + row1)) * DD + h * 64;
    __half* o2 = o1 + 8 * DD;
#pragma unroll
    for (int nf = 0; nf < 8; nf++) {
        *reinterpret_cast<__half2*>(&o1[nf * 8 + t4 * 2]) =
            __floats2half2_rn(acc[nf][0] * i1, acc[nf][1] * i1);
        *reinterpret_cast<__half2*>(&o2[nf * 8 + t4 * 2]) =
            __floats2half2_rn(acc[nf][2] * i2, acc[nf][3] * i2);
    }
}

// ---------------- launch ----------------
extern "C" void kernel_launch(void* const* d_in, const int* in_sizes, int n_in,
                              void* d_out, int out_size)
{
    (void)in_sizes; (void)n_in; (void)out_size;
    const float* query = (const float*)d_in[0];
    const float* value = (const float*)d_in[1];
    const int*   amask = (const int*)d_in[2];
    const float* Wq = (const float*)d_in[3];
    const float* bq = (const float*)d_in[4];
    const float* Wk = (const float*)d_in[5];
    const float* bk = (const float*)d_in[6];
    const float* Wv = (const float*)d_in[7];
    const float* bv = (const float*)d_in[8];
    const float* Wo = (const float*)d_in[9];
    const float* bo = (const float*)d_in[10];
    float* out = (float*)d_out;

    __half *hq, *hv, *hWq, *hWo, *hWkv, *pq, *pk, *pv, *pctx;
    cudaGetSymbolAddress((void**)&hq, g_hquery);
    cudaGetSymbolAddress((void**)&hv, g_hvalue);
    cudaGetSymbolAddress((void**)&hWq, g_hWq);
    cudaGetSymbolAddress((void**)&hWo, g_hWo);
    cudaGetSymbolAddress((void**)&hWkv, g_hWkv);
    cudaGetSymbolAddress((void**)&pq, g_q);
    cudaGetSymbolAddress((void**)&pk, g_k);
    cudaGetSymbolAddress((void**)&pv, g_v);
    cudaGetSymbolAddress((void**)&pctx, g_ctx);

    const int M = BB * SS;               // 8192
    const int NIN = M * DD;

    cvt_in<<<dim3((NIN / 4 + 255) / 256, 2), 256>>>(query, value, hq, hv, NIN / 4);
    cvt_w<<<dim3((DD * DD / 8 + 255) / 256, 4), 256>>>(Wq, Wk, Wv, Wo, hWq, hWkv, hWo);

    gemm_h<1><<<dim3(4, 64), 256>>>(hq, hWq, bq, nullptr, pq, nullptr,
                                    M, DD, DD, 0.125f);
    gemm_h<2><<<dim3(8, 64), 256>>>(hv, hWkv, bk, bv, pk, pv,
                                    M, DD, 2 * DD, 1.0f);

    cudaFuncSetAttribute(attn_hmma, cudaFuncAttributeMaxDynamicSharedMemorySize, SMEM_B);
    attn_hmma<<<dim3(SS / 64, BB * HH), 128, SMEM_B>>>(pq, pk, pv, amask, pctx);

    gemm_h<0><<<dim3(4, 64), 256>>>(pctx, hWo, bo, nullptr, out, nullptr,
                                    M, DD, DD, 1.0f);
}